// round 6
// baseline (speedup 1.0000x reference)
#include <cuda_runtime.h>

static constexpr int AB    = 128;    // A*B
static constexpr int NROWS = 1024;   // N = M
static constexpr int KD    = 64;
static constexpr int RQ    = KD / 4; // float4 per row = 16
static constexpr int CHV   = 8;      // v-sum chunks per ab (128 rows each)
static constexpr int CHU   = 8;      // u-sum chunks per ab (128 rows each)

// Partial column sums (fixed-order, deterministic)
__device__ float4 g_part_v[AB * CHV * RQ];   // [ab][chunk][q]
__device__ float4 g_part_u[AB * CHU * RQ];   // [ab][chunk][q]

// ---------------------------------------------------------------------------
// K1: v column sums. grid = 1024 (128 ab x 8 chunks) -> ~55 warps/SM resident
// (was 512 blocks = 42% occ, latency-bound). block = 256 = 16 row-groups x
// 16 float4-lanes; 8 independent float4 loads/thread, 4-level smem tree.
// Default cache policy: v must STAY in L2 for K3.
// ---------------------------------------------------------------------------
__global__ void __launch_bounds__(256) vsum_kernel(const float4* __restrict__ v) {
    const int b     = blockIdx.x;      // 0..1023
    const int ab    = b >> 3;
    const int chunk = b & 7;
    const float4* __restrict__ base = v + ((size_t)ab * NROWS + chunk * 128) * RQ;

    const int q = threadIdx.x & 15;
    const int r = threadIdx.x >> 4;    // 0..15

    float4 s = make_float4(0.f, 0.f, 0.f, 0.f);
#pragma unroll
    for (int i = 0; i < 8; i++) {
        const float4 x = base[(size_t)(r + i * 16) * RQ + q];
        s.x += x.x; s.y += x.y; s.z += x.z; s.w += x.w;
    }

    __shared__ float4 sred[16][RQ];
    sred[r][q] = s;
    __syncthreads();
#pragma unroll
    for (int stride = 8; stride > 0; stride >>= 1) {
        if (r < stride) {
            const float4 o = sred[r + stride][q];
            sred[r][q].x += o.x; sred[r][q].y += o.y;
            sred[r][q].z += o.z; sred[r][q].w += o.w;
        }
        __syncthreads();
    }
    if (r == 0) g_part_v[(ab * CHV + chunk) * RQ + q] = sred[0][q];
}

// ---------------------------------------------------------------------------
// K2: single pass over u. Per warp: 16 rows (8 float4 slots, half=lane>>4,
// q=lane&15). Computes (a) row dots vs v_sum -> gate -> streamed store of
// gated u; (b) this block's 128-row column partial -> g_part_u.
// grid = 1024 (128 ab x 8 chunks), block = 256 (8 warps x 16 rows).
// u is read exactly once ever -> __ldcs (evict-first, preserves L2 for v).
// ---------------------------------------------------------------------------
__global__ void __launch_bounds__(256) usum_gateu_kernel(const float4* __restrict__ u,
                                                         float4* __restrict__ out) {
    const int blk   = blockIdx.x;       // 0..1023
    const int ab    = blk >> 3;
    const int chunk = blk & 7;
    const int warp  = threadIdx.x >> 5; // 0..7
    const int lane  = threadIdx.x & 31;
    const int half  = lane >> 4;
    const int q     = lane & 15;

    // v_sum[ab] from its 8 chunk partials (L2-hot, tiny)
    const float4* __restrict__ Pv = g_part_v + (size_t)ab * CHV * RQ + q;
    float4 sv = __ldg(Pv);
#pragma unroll
    for (int c = 1; c < CHV; c++) {
        const float4 o = __ldg(Pv + c * RQ);
        sv.x += o.x; sv.y += o.y; sv.z += o.z; sv.w += o.w;
    }

    const int    row0 = ab * NROWS + chunk * 128 + warp * 16;
    const size_t base = (size_t)row0 * RQ + (size_t)half * RQ + q;

    float4 x[8];
#pragma unroll
    for (int j = 0; j < 8; j++) x[j] = __ldcs(u + base + (size_t)j * (2 * RQ));

    // (b) column partial: per-lane sum over the 8 slots, then fold halves
    float4 cs = make_float4(0.f, 0.f, 0.f, 0.f);
#pragma unroll
    for (int j = 0; j < 8; j++) {
        cs.x += x[j].x; cs.y += x[j].y; cs.z += x[j].z; cs.w += x[j].w;
    }
    cs.x += __shfl_xor_sync(0xffffffffu, cs.x, 16);
    cs.y += __shfl_xor_sync(0xffffffffu, cs.y, 16);
    cs.z += __shfl_xor_sync(0xffffffffu, cs.z, 16);
    cs.w += __shfl_xor_sync(0xffffffffu, cs.w, 16);

    __shared__ float4 sred[8][RQ];     // per-warp 16-row partials
    if (half == 0) sred[warp][q] = cs;
    __syncthreads();
    if (threadIdx.x < 16) {            // serial 8-term sum, fixed order
        float4 a = sred[0][q];
#pragma unroll
        for (int wgi = 1; wgi < 8; wgi++) {
            const float4 o = sred[wgi][q];
            a.x += o.x; a.y += o.y; a.z += o.z; a.w += o.w;
        }
        g_part_u[(ab * CHU + chunk) * RQ + q] = a;
    }

    // (a) gate: row dot vs sv, 4-level xor tree inside the 16-lane segment
    float p[8];
#pragma unroll
    for (int j = 0; j < 8; j++)
        p[j] = fmaf(x[j].x, sv.x,
                fmaf(x[j].y, sv.y,
                 fmaf(x[j].z, sv.z, x[j].w * sv.w)));
#pragma unroll
    for (int m = 8; m; m >>= 1)
#pragma unroll
        for (int j = 0; j < 8; j++)
            p[j] += __shfl_xor_sync(0xffffffffu, p[j], m);

#pragma unroll
    for (int j = 0; j < 8; j++) {
        const float g = (p[j] > 0.f) ? 1.f : 0.f;
        __stcs(out + base + (size_t)j * (2 * RQ),
               make_float4(x[j].x * g, x[j].y * g, x[j].z * g, x[j].w * g));
    }
}

// ---------------------------------------------------------------------------
// K3: gate v with u_sum. Same warp layout as K2 minus the partial-sum work.
// v reads should be L2-hot (K1 streamed it; K2's u was evict-first).
// grid = 1024, block = 256.
// ---------------------------------------------------------------------------
__global__ void __launch_bounds__(256) gatev_kernel(const float4* __restrict__ v,
                                                    float4* __restrict__ outv) {
    const int blk   = blockIdx.x;
    const int ab    = blk >> 3;
    const int chunk = blk & 7;
    const int warp  = threadIdx.x >> 5;
    const int lane  = threadIdx.x & 31;
    const int half  = lane >> 4;
    const int q     = lane & 15;

    // u_sum[ab] from its 8 chunk partials
    const float4* __restrict__ Pu = g_part_u + (size_t)ab * CHU * RQ + q;
    float4 su = __ldg(Pu);
#pragma unroll
    for (int c = 1; c < CHU; c++) {
        const float4 o = __ldg(Pu + c * RQ);
        su.x += o.x; su.y += o.y; su.z += o.z; su.w += o.w;
    }

    const int    row0 = ab * NROWS + chunk * 128 + warp * 16;
    const size_t base = (size_t)row0 * RQ + (size_t)half * RQ + q;

    float4 x[8];
#pragma unroll
    for (int j = 0; j < 8; j++) x[j] = __ldcs(v + base + (size_t)j * (2 * RQ));

    float p[8];
#pragma unroll
    for (int j = 0; j < 8; j++)
        p[j] = fmaf(x[j].x, su.x,
                fmaf(x[j].y, su.y,
                 fmaf(x[j].z, su.z, x[j].w * su.w)));
#pragma unroll
    for (int m = 8; m; m >>= 1)
#pragma unroll
        for (int j = 0; j < 8; j++)
            p[j] += __shfl_xor_sync(0xffffffffu, p[j], m);

#pragma unroll
    for (int j = 0; j < 8; j++) {
        const float g = (p[j] > 0.f) ? 1.f : 0.f;
        __stcs(outv + base + (size_t)j * (2 * RQ),
               make_float4(x[j].x * g, x[j].y * g, x[j].z * g, x[j].w * g));
    }
}

// ---------------------------------------------------------------------------
extern "C" void kernel_launch(void* const* d_in, const int* in_sizes, int n_in,
                              void* d_out, int out_size) {
    const float4* u = (const float4*)d_in[0];
    const float4* v = (const float4*)d_in[1];
    float4* out  = (float4*)d_out;
    float4* outv = out + (size_t)AB * NROWS * RQ;   // second half: gated v

    vsum_kernel      <<<AB * CHV, 256>>>(v);
    usum_gateu_kernel<<<AB * CHU, 256>>>(u, out);
    gatev_kernel     <<<AB * CHU, 256>>>(v, outv);
}

// round 9
// speedup vs baseline: 1.3774x; 1.3774x over previous
#include <cuda_runtime.h>

static constexpr int AB    = 128;    // A*B
static constexpr int NROWS = 1024;   // N = M
static constexpr int KD    = 64;
static constexpr int RQ    = KD / 4; // float4 per row = 16
static constexpr int CHV   = 4;      // v-sum chunks per ab (256 rows each)
static constexpr int CHU   = 8;      // u-sum chunks per ab (128 rows each)

// Partial column sums (fixed-order, deterministic)
__device__ float4 g_part_v[AB * CHV * RQ];   // [ab][chunk][q]
__device__ float4 g_part_u[AB * CHU * RQ];   // [ab][chunk][q]

// 32-byte read-only load with L2 evict-last hint (the only vector width this
// modifier accepts is 256-bit: .v8.b32). Keeps v resident in L2 for K3.
__device__ __forceinline__ void ldg_el_32B(const float* p, float4& a, float4& b) {
    unsigned r0, r1, r2, r3, r4, r5, r6, r7;
    asm volatile(
        "ld.global.nc.L2::evict_last.v8.b32 {%0,%1,%2,%3,%4,%5,%6,%7}, [%8];"
        : "=r"(r0), "=r"(r1), "=r"(r2), "=r"(r3),
          "=r"(r4), "=r"(r5), "=r"(r6), "=r"(r7)
        : "l"(p));
    a.x = __uint_as_float(r0); a.y = __uint_as_float(r1);
    a.z = __uint_as_float(r2); a.w = __uint_as_float(r3);
    b.x = __uint_as_float(r4); b.y = __uint_as_float(r5);
    b.z = __uint_as_float(r6); b.w = __uint_as_float(r7);
}

// ---------------------------------------------------------------------------
// K1: v column sums. grid = 512 (128 ab x 4 chunks of 256 rows), block = 256
// = 32 row-groups x 8 lane-chunks of 32B (8 x 32B = one 256B row, fully
// coalesced). 8 independent 32B evict_last loads per thread, then a 5-level
// smem tree over the 32 row-groups. v stays L2-resident for K3.
// ---------------------------------------------------------------------------
__global__ void __launch_bounds__(256) vsum_kernel(const float* __restrict__ v) {
    const int b     = blockIdx.x;      // 0..511
    const int ab    = b >> 2;
    const int chunk = b & 3;
    const float* __restrict__ base =
        v + ((size_t)ab * NROWS + chunk * 256) * KD;

    const int c8 = threadIdx.x & 7;    // 32B column chunk (8 floats)
    const int r  = threadIdx.x >> 3;   // 0..31 row group

    float4 sa = make_float4(0.f, 0.f, 0.f, 0.f);
    float4 sb = make_float4(0.f, 0.f, 0.f, 0.f);
#pragma unroll
    for (int i = 0; i < 8; i++) {
        float4 xa, xb;
        ldg_el_32B(base + (size_t)(r + i * 32) * KD + c8 * 8, xa, xb);
        sa.x += xa.x; sa.y += xa.y; sa.z += xa.z; sa.w += xa.w;
        sb.x += xb.x; sb.y += xb.y; sb.z += xb.z; sb.w += xb.w;
    }

    __shared__ float4 sred[32][16];    // [row-group][float4 col] = 8 KB
    sred[r][c8 * 2 + 0] = sa;
    sred[r][c8 * 2 + 1] = sb;
    __syncthreads();
    // tree over 32 row groups; 256 threads cover 32x16/2 pairs per level
#pragma unroll
    for (int stride = 16; stride > 0; stride >>= 1) {
        if (r < stride) {
#pragma unroll
            for (int h = 0; h < 2; h++) {
                const int qq = c8 * 2 + h;
                const float4 o = sred[r + stride][qq];
                sred[r][qq].x += o.x; sred[r][qq].y += o.y;
                sred[r][qq].z += o.z; sred[r][qq].w += o.w;
            }
        }
        __syncthreads();
    }
    if (r == 0) {
        g_part_v[(ab * CHV + chunk) * RQ + c8 * 2 + 0] = sred[0][c8 * 2 + 0];
        g_part_v[(ab * CHV + chunk) * RQ + c8 * 2 + 1] = sred[0][c8 * 2 + 1];
    }
}

// ---------------------------------------------------------------------------
// K2: single pass over u. Per warp: 16 rows (8 float4 slots, half=lane>>4,
// q=lane&15). (a) row dots vs v_sum -> gate -> streamed store of gated u;
// (b) this block's 128-row column partial -> g_part_u.
// grid = 1024 (128 ab x 8 chunks), block = 256.
// u read exactly once -> __ldcs (evict-first, preserves v in L2);
// stores __stcs (never re-read).
// ---------------------------------------------------------------------------
__global__ void __launch_bounds__(256) usum_gateu_kernel(const float4* __restrict__ u,
                                                         float4* __restrict__ out) {
    const int blk   = blockIdx.x;       // 0..1023
    const int ab    = blk >> 3;
    const int chunk = blk & 7;
    const int warp  = threadIdx.x >> 5; // 0..7
    const int lane  = threadIdx.x & 31;
    const int half  = lane >> 4;
    const int q     = lane & 15;

    // v_sum[ab] from its 4 chunk partials (L2-hot, tiny)
    const float4* __restrict__ Pv = g_part_v + (size_t)ab * CHV * RQ + q;
    float4 sv = __ldg(Pv);
#pragma unroll
    for (int c = 1; c < CHV; c++) {
        const float4 o = __ldg(Pv + c * RQ);
        sv.x += o.x; sv.y += o.y; sv.z += o.z; sv.w += o.w;
    }

    const int    row0 = ab * NROWS + chunk * 128 + warp * 16;
    const size_t base = (size_t)row0 * RQ + (size_t)half * RQ + q;

    float4 x[8];
#pragma unroll
    for (int j = 0; j < 8; j++) x[j] = __ldcs(u + base + (size_t)j * (2 * RQ));

    // (b) column partial: per-lane sum over the 8 slots, then fold halves
    float4 cs = make_float4(0.f, 0.f, 0.f, 0.f);
#pragma unroll
    for (int j = 0; j < 8; j++) {
        cs.x += x[j].x; cs.y += x[j].y; cs.z += x[j].z; cs.w += x[j].w;
    }
    cs.x += __shfl_xor_sync(0xffffffffu, cs.x, 16);
    cs.y += __shfl_xor_sync(0xffffffffu, cs.y, 16);
    cs.z += __shfl_xor_sync(0xffffffffu, cs.z, 16);
    cs.w += __shfl_xor_sync(0xffffffffu, cs.w, 16);

    __shared__ float4 sred[8][RQ];     // per-warp 16-row partials
    if (half == 0) sred[warp][q] = cs;
    __syncthreads();
    if (threadIdx.x < 16) {            // serial 8-term sum, fixed order
        float4 a = sred[0][q];
#pragma unroll
        for (int wgi = 1; wgi < 8; wgi++) {
            const float4 o = sred[wgi][q];
            a.x += o.x; a.y += o.y; a.z += o.z; a.w += o.w;
        }
        g_part_u[(ab * CHU + chunk) * RQ + q] = a;
    }

    // (a) gate: row dot vs sv, 4-level xor tree inside the 16-lane segment
    float p[8];
#pragma unroll
    for (int j = 0; j < 8; j++)
        p[j] = fmaf(x[j].x, sv.x,
                fmaf(x[j].y, sv.y,
                 fmaf(x[j].z, sv.z, x[j].w * sv.w)));
#pragma unroll
    for (int m = 8; m; m >>= 1)
#pragma unroll
        for (int j = 0; j < 8; j++)
            p[j] += __shfl_xor_sync(0xffffffffu, p[j], m);

#pragma unroll
    for (int j = 0; j < 8; j++) {
        const float g = (p[j] > 0.f) ? 1.f : 0.f;
        __stcs(out + base + (size_t)j * (2 * RQ),
               make_float4(x[j].x * g, x[j].y * g, x[j].z * g, x[j].w * g));
    }
}

// ---------------------------------------------------------------------------
// K3: gate v with u_sum. v reads should be L2-hot (K1 loaded v evict_last;
// K2's u was evict-first, stores streaming) -> essentially write-bound.
// grid = 1024, block = 256.
// ---------------------------------------------------------------------------
__global__ void __launch_bounds__(256) gatev_kernel(const float4* __restrict__ v,
                                                    float4* __restrict__ outv) {
    const int blk   = blockIdx.x;
    const int ab    = blk >> 3;
    const int chunk = blk & 7;
    const int warp  = threadIdx.x >> 5;
    const int lane  = threadIdx.x & 31;
    const int half  = lane >> 4;
    const int q     = lane & 15;

    // u_sum[ab] from its 8 chunk partials
    const float4* __restrict__ Pu = g_part_u + (size_t)ab * CHU * RQ + q;
    float4 su = __ldg(Pu);
#pragma unroll
    for (int c = 1; c < CHU; c++) {
        const float4 o = __ldg(Pu + c * RQ);
        su.x += o.x; su.y += o.y; su.z += o.z; su.w += o.w;
    }

    const int    row0 = ab * NROWS + chunk * 128 + warp * 16;
    const size_t base = (size_t)row0 * RQ + (size_t)half * RQ + q;

    float4 x[8];
#pragma unroll
    for (int j = 0; j < 8; j++) x[j] = __ldcs(v + base + (size_t)j * (2 * RQ));

    float p[8];
#pragma unroll
    for (int j = 0; j < 8; j++)
        p[j] = fmaf(x[j].x, su.x,
                fmaf(x[j].y, su.y,
                 fmaf(x[j].z, su.z, x[j].w * su.w)));
#pragma unroll
    for (int m = 8; m; m >>= 1)
#pragma unroll
        for (int j = 0; j < 8; j++)
            p[j] += __shfl_xor_sync(0xffffffffu, p[j], m);

#pragma unroll
    for (int j = 0; j < 8; j++) {
        const float g = (p[j] > 0.f) ? 1.f : 0.f;
        __stcs(outv + base + (size_t)j * (2 * RQ),
               make_float4(x[j].x * g, x[j].y * g, x[j].z * g, x[j].w * g));
    }
}

// ---------------------------------------------------------------------------
extern "C" void kernel_launch(void* const* d_in, const int* in_sizes, int n_in,
                              void* d_out, int out_size) {
    const float*  vf = (const float*)d_in[1];
    const float4* u  = (const float4*)d_in[0];
    const float4* v  = (const float4*)d_in[1];
    float4* out  = (float4*)d_out;
    float4* outv = out + (size_t)AB * NROWS * RQ;   // second half: gated v

    vsum_kernel      <<<AB * CHV, 256>>>(vf);
    usum_gateu_kernel<<<AB * CHU, 256>>>(u, out);
    gatev_kernel     <<<AB * CHU, 256>>>(v, outv);
}